// round 1
// baseline (speedup 1.0000x reference)
#include <cuda_runtime.h>
#include <cuda_bf16.h>

#define BB 64
#define NN 2048
#define MM 64

// Transposed cost scratch: costT[b][m][n] (float storage, exact f32 values;
// Hungarian arithmetic is done in double, widening is exact).
__device__ float g_costT[BB * MM * NN];

// ---------------------------------------------------------------------------
// Kernel 1: cost[b][n][m] = -ps[b][n][gs[b][m]] + sum_d |pb[b][n][d]-gb[b][m][d]|
// Each block: one batch b, 64 consecutive n's. 512 threads, 8 elems/thread.
// Writes cost (n-major, coalesced) and g_costT (m-major, coalesced via smem tile).
// ---------------------------------------------------------------------------
__global__ void __launch_bounds__(512) cost_kernel(
    const float* __restrict__ ps, const float* __restrict__ pb,
    const int* __restrict__ gs, const float* __restrict__ gb,
    float* __restrict__ cost_out)
{
    const int b  = blockIdx.y;
    const int n0 = blockIdx.x * 64;
    const int t  = threadIdx.x;

    __shared__ float s_ps[64 * 2];
    __shared__ float s_pb[64 * 4];
    __shared__ float s_gb[64 * 4];
    __shared__ int   s_gs[64];
    __shared__ float tile[64][65];   // [n_local][m], padded to avoid bank conflicts

    if (t < 128) s_ps[t] = ps[(b * NN + n0) * 2 + t];
    if (t < 256) s_pb[t] = pb[(b * NN + n0) * 4 + t];
    else         s_gb[t - 256] = gb[b * MM * 4 + (t - 256)];
    if (t < 64)  s_gs[t] = gs[b * MM + t];
    __syncthreads();

    const int out_base = (b * NN + n0) * MM;   // contiguous 4096-elem tile
#pragma unroll
    for (int k = 0; k < 8; k++) {
        int idx = t + k * 512;            // 0..4095, n_local = idx/64, m = idx%64
        int nl = idx >> 6;
        int m  = idx & 63;
        float pres = -s_ps[nl * 2 + s_gs[m]];
        float l1 = fabsf(s_pb[nl * 4 + 0] - s_gb[m * 4 + 0]);
        l1 = l1 + fabsf(s_pb[nl * 4 + 1] - s_gb[m * 4 + 1]);
        l1 = l1 + fabsf(s_pb[nl * 4 + 2] - s_gb[m * 4 + 2]);
        l1 = l1 + fabsf(s_pb[nl * 4 + 3] - s_gb[m * 4 + 3]);
        float cv = pres + l1;
        tile[nl][m] = cv;
        cost_out[out_base + idx] = cv;
    }
    __syncthreads();

    // Transposed write: costT[b][m][n0+nl], nl fastest -> coalesced.
    const int ct_base = b * (MM * NN) + n0;
#pragma unroll
    for (int k = 0; k < 8; k++) {
        int idx = t + k * 512;            // m = idx/64, nl = idx%64
        int m  = idx >> 6;
        int nl = idx & 63;
        g_costT[ct_base + m * NN + nl] = tile[nl][m];
    }
}

// ---------------------------------------------------------------------------
// Kernel 2: exact replication of the reference's (degenerate) Hungarian loop.
// One block per batch, 512 threads. All dual arithmetic in double, matching
// the reference's float64 order of operations:
//   cur = (cost - u[i0]) - v[j];  u[p[used]] += delta;  v[used] -= delta.
// Argmin tie-break: first (lowest) index, like np.argmin.
// ---------------------------------------------------------------------------
__global__ void __launch_bounds__(512) hungarian_kernel(
    float* __restrict__ out_row, float* __restrict__ out_col)
{
    const int b = blockIdx.x;
    const int t = threadIdx.x;
    const float* crow_base = g_costT + (size_t)b * MM * NN;

    __shared__ double s_v[NN + 1];
    __shared__ double s_u[MM + 1];
    __shared__ int    s_p[NN + 1];
    __shared__ unsigned char s_used[NN + 1];
    __shared__ int    s_usedlist[MM + 2];
    __shared__ double s_wmin[16];
    __shared__ int    s_widx[16];
    __shared__ int    s_j0, s_i0, s_ucount;
    __shared__ double s_delta;
    __shared__ int    s_col4row[MM];

    const double DINF = 1e300;

    for (int j = t; j <= NN; j += 512) { s_v[j] = 0.0; s_p[j] = 0; }
    if (t <= MM) s_u[t] = 0.0;
    __syncthreads();

    for (int i = 1; i <= MM; i++) {
        for (int j = t; j <= NN; j += 512) s_used[j] = 0;
        if (t == 0) { s_p[0] = i; s_j0 = 0; s_ucount = 0; }
        __syncthreads();

        int done = 0;
        while (!done) {
            if (t == 0) {
                int j0 = s_j0;
                s_used[j0] = 1;
                s_usedlist[s_ucount++] = j0;
                s_i0 = s_p[j0];
            }
            __syncthreads();

            const int i0 = s_i0;
            const double u_i0 = s_u[i0];
            const float* crow = crow_base + (size_t)(i0 - 1) * NN;

            // parallel scan over free columns
            double lmin = DINF;
            int    lidx = NN + 2;
#pragma unroll
            for (int k = 0; k < 4; k++) {
                int j = t + 1 + k * 512;
                if (!s_used[j]) {
                    double cur = ((double)crow[j - 1] - u_i0) - s_v[j];
                    if (cur < lmin) { lmin = cur; lidx = j; }
                }
            }
            // warp reduce (min value, then min index on ties)
#pragma unroll
            for (int off = 16; off > 0; off >>= 1) {
                double om = __shfl_down_sync(0xffffffffu, lmin, off);
                int    oi = __shfl_down_sync(0xffffffffu, lidx, off);
                if (om < lmin || (om == lmin && oi < lidx)) { lmin = om; lidx = oi; }
            }
            if ((t & 31) == 0) { s_wmin[t >> 5] = lmin; s_widx[t >> 5] = lidx; }
            __syncthreads();
            if (t < 32) {
                double m2 = (t < 16) ? s_wmin[t] : DINF;
                int    i2 = (t < 16) ? s_widx[t] : NN + 2;
#pragma unroll
                for (int off = 8; off > 0; off >>= 1) {
                    double om = __shfl_down_sync(0xffffffffu, m2, off);
                    int    oi = __shfl_down_sync(0xffffffffu, i2, off);
                    if (om < m2 || (om == m2 && oi < i2)) { m2 = om; i2 = oi; }
                }
                if (t == 0) { s_delta = m2; s_j0 = i2; }
            }
            __syncthreads();

            const double delta = s_delta;
            const int    j1    = s_j0;
            const int    uc    = s_ucount;
            // dual update over used columns (distinct rows -> no conflicts)
            if (t < uc) {
                int j = s_usedlist[t];
                s_u[s_p[j]] += delta;
                s_v[j]      -= delta;
            }
            int pj1 = s_p[j1];   // read before any write to s_p
            __syncthreads();
            if (pj1 == 0) {
                if (t == 0) s_p[j1] = i;  // assign row i to free column j1
                done = 1;
            }
            __syncthreads();
        }
    }

    // col4row[row-1] = col-1 for matched columns
    for (int j = t + 1; j <= NN; j += 512) {
        int pj = s_p[j];
        if (pj > 0) s_col4row[pj - 1] = j - 1;
    }
    __syncthreads();

    // argsort by prediction index (all distinct): rank = count of smaller preds
    if (t < MM) {
        int pred = s_col4row[t];
        int rank = 0;
#pragma unroll
        for (int g = 0; g < MM; g++) rank += (s_col4row[g] < pred) ? 1 : 0;
        out_row[b * MM + rank] = (float)pred;
        out_col[b * MM + rank] = (float)t;
    }
}

extern "C" void kernel_launch(void* const* d_in, const int* in_sizes, int n_in,
                              void* d_out, int out_size)
{
    const float* ps = (const float*)d_in[0];   // [64,2048,2]
    const float* pb = (const float*)d_in[1];   // [64,2048,4]
    const int*   gs = (const int*)  d_in[2];   // [64,64]
    const float* gb = (const float*)d_in[3];   // [64,64,4]
    float* out = (float*)d_out;

    dim3 g1(NN / 64, BB);
    cost_kernel<<<g1, 512>>>(ps, pb, gs, gb, out);

    const long cost_elems = (long)BB * NN * MM;       // 8388608
    const long idx_elems  = (long)BB * MM;            // 4096
    if (out_size >= cost_elems + 2 * idx_elems) {
        float* row_out = out + cost_elems;
        float* col_out = row_out + idx_elems;
        hungarian_kernel<<<BB, 512>>>(row_out, col_out);
    }
}

// round 2
// speedup vs baseline: 1.5218x; 1.5218x over previous
#include <cuda_runtime.h>
#include <cuda_bf16.h>

#define BB 64
#define NN 2048
#define MM 64
#define TPB 128      // hungarian threads per block (4 warps)
#define CPT 16       // columns per thread (TPB*CPT == NN)

// Transposed cost scratch: costT[b][m][n] (float; exact f32 values).
__device__ float g_costT[BB * MM * NN];

// ---------------------------------------------------------------------------
// Kernel 1: cost[b][n][m] = -ps[b][n][gs[b][m]] + sum_d |pb[b][n][d]-gb[b][m][d]|
// ---------------------------------------------------------------------------
__global__ void __launch_bounds__(512) cost_kernel(
    const float* __restrict__ ps, const float* __restrict__ pb,
    const int* __restrict__ gs, const float* __restrict__ gb,
    float* __restrict__ cost_out)
{
    const int b  = blockIdx.y;
    const int n0 = blockIdx.x * 64;
    const int t  = threadIdx.x;

    __shared__ float s_ps[64 * 2];
    __shared__ float s_pb[64 * 4];
    __shared__ float s_gb[64 * 4];
    __shared__ int   s_gs[64];
    __shared__ float tile[64][65];

    if (t < 128) s_ps[t] = ps[(b * NN + n0) * 2 + t];
    if (t < 256) s_pb[t] = pb[(b * NN + n0) * 4 + t];
    else         s_gb[t - 256] = gb[b * MM * 4 + (t - 256)];
    if (t < 64)  s_gs[t] = gs[b * MM + t];
    __syncthreads();

    const int out_base = (b * NN + n0) * MM;
#pragma unroll
    for (int k = 0; k < 8; k++) {
        int idx = t + k * 512;
        int nl = idx >> 6;
        int m  = idx & 63;
        float pres = -s_ps[nl * 2 + s_gs[m]];
        float l1 = fabsf(s_pb[nl * 4 + 0] - s_gb[m * 4 + 0]);
        l1 = l1 + fabsf(s_pb[nl * 4 + 1] - s_gb[m * 4 + 1]);
        l1 = l1 + fabsf(s_pb[nl * 4 + 2] - s_gb[m * 4 + 2]);
        l1 = l1 + fabsf(s_pb[nl * 4 + 3] - s_gb[m * 4 + 3]);
        float cv = pres + l1;
        tile[nl][m] = cv;
        cost_out[out_base + idx] = cv;
    }
    __syncthreads();

    const int ct_base = b * (MM * NN) + n0;
#pragma unroll
    for (int k = 0; k < 8; k++) {
        int idx = t + k * 512;
        int m  = idx >> 6;
        int nl = idx & 63;
        g_costT[ct_base + m * NN + nl] = tile[nl][m];
    }
}

// monotone map float -> uint (order preserving for all finite values and inf)
__device__ __forceinline__ unsigned fmap(float x) {
    unsigned u = __float_as_uint(x);
    return (u & 0x80000000u) ? ~u : (u | 0x80000000u);
}
__device__ __forceinline__ float funmap(unsigned m) {
    unsigned u = (m & 0x80000000u) ? (m ^ 0x80000000u) : ~m;
    return __uint_as_float(u);
}

// ---------------------------------------------------------------------------
// Kernel 2: exact replication of the reference's degenerate Hungarian loop.
// 4 warps; v duals register-resident; fp32 scan + exact f64 candidate verify.
// ---------------------------------------------------------------------------
__global__ void __launch_bounds__(TPB) hungarian_kernel(
    float* __restrict__ out_row, float* __restrict__ out_col)
{
    const int b    = blockIdx.x;
    const int t    = threadIdx.x;
    const int w    = t >> 5;
    const int lane = t & 31;
    const float* crow_base = g_costT + (size_t)b * MM * NN;

    __shared__ double s_u[MM + 1];
    __shared__ int    s_p[NN + 1];
    __shared__ unsigned s_wmin[4];
    __shared__ int    s_ncand;
    __shared__ double s_cval[128];
    __shared__ int    s_cidx[128];
    __shared__ double s_delta;
    __shared__ int    s_j1, s_pj1;
    __shared__ int    s_col4row[MM];

    const float INFF = __int_as_float(0x7f800000);

    double v_loc[CPT];
    float  vf_loc[CPT];
#pragma unroll
    for (int k = 0; k < CPT; k++) { v_loc[k] = 0.0; vf_loc[k] = 0.0f; }

    for (int j = t; j <= NN; j += TPB) s_p[j] = 0;
    if (t <= MM) s_u[t] = 0.0;
    if (t == 0) s_ncand = 0;
    __syncthreads();

    const int jbase = t * CPT + 1;   // first 1-based column owned by this thread
    float Dsum = 0.0f;               // running sum of |delta| for error band

    for (int i = 1; i <= MM; i++) {
        unsigned usedMask = 0;
        int rowOf[CPT];
        int j0 = 0;
        int i0 = i;
        double u_i0 = s_u[i];        // == 0.0 for a fresh row (row i never on a prior chain)

        for (;;) {
            // mark column j0 used (j0==0 is the virtual column, handled by t==0 below)
            if (j0 >= jbase && j0 < jbase + CPT) {
                int km = j0 - jbase;
                usedMask |= (1u << km);
#pragma unroll
                for (int kk = 0; kk < CPT; kk++) if (kk == km) rowOf[kk] = i0;
            }
            const float uf = (float)u_i0;

            // load this row's 16 costs (coalesced float4 x4)
            const float4* r4 = reinterpret_cast<const float4*>(
                crow_base + (size_t)(i0 - 1) * NN + (jbase - 1));
            float4 c0 = __ldg(r4 + 0);
            float4 c1 = __ldg(r4 + 1);
            float4 c2 = __ldg(r4 + 2);
            float4 c3 = __ldg(r4 + 3);
            float cc[CPT] = { c0.x, c0.y, c0.z, c0.w,
                              c1.x, c1.y, c1.z, c1.w,
                              c2.x, c2.y, c2.z, c2.w,
                              c3.x, c3.y, c3.z, c3.w };

            float cur[CPT];
            float m32 = INFF;
#pragma unroll
            for (int k = 0; k < CPT; k++) {
                float x = (cc[k] - uf) - vf_loc[k];
                if (usedMask & (1u << k)) x = INFF;
                cur[k] = x;
                m32 = fminf(m32, x);
            }

            // block min of m32 (mapped-uint warp redux + tiny cross-warp stage)
            unsigned mu = fmap(m32);
            mu = __reduce_min_sync(0xffffffffu, mu);
            if (lane == 0) s_wmin[w] = mu;
            __syncthreads();                                   // B1
            unsigned mm_ = min(min(s_wmin[0], s_wmin[1]),
                               min(s_wmin[2], s_wmin[3]));
            float mblk = funmap(mm_);

            // conservative fp32-error band; exact f64 verify on candidates
            float band = 2e-6f + 4e-7f * Dsum + 2e-7f * fabsf(mblk);
            float thr  = mblk + band;
#pragma unroll
            for (int k = 0; k < CPT; k++) {
                if (cur[k] <= thr && !(usedMask & (1u << k))) {
                    double cur64 = ((double)cc[k] - u_i0) - v_loc[k];
                    int slot = atomicAdd(&s_ncand, 1);
                    if (slot < 128) { s_cval[slot] = cur64; s_cidx[slot] = jbase + k; }
                }
            }
            __syncthreads();                                   // B2

            if (t == 0) {
                int nc = s_ncand; if (nc > 128) nc = 128;
                double best = 1e308; int bidx = NN + 2;
                for (int q = 0; q < nc; q++) {
                    double kv = s_cval[q]; int ix = s_cidx[q];
                    if (kv < best || (kv == best && ix < bidx)) { best = kv; bidx = ix; }
                }
                s_delta = best;
                s_j1    = bidx;
                s_pj1   = s_p[bidx];
                s_ncand = 0;
            }
            __syncthreads();                                   // B3

            const double delta = s_delta;
            const int    j1    = s_j1;
            const int    pj1   = s_pj1;
            Dsum += fabsf((float)delta);

            // dual updates for ALL currently-used columns (reference semantics)
#pragma unroll
            for (int k = 0; k < CPT; k++) {
                if (usedMask & (1u << k)) {
                    v_loc[k] -= delta;
                    vf_loc[k] = (float)v_loc[k];
                    s_u[rowOf[k]] += delta;       // distinct rows -> no conflicts
                }
            }
            if (t == 0) s_u[i] += delta;          // virtual column 0: p[0] = i
            if (pj1 == 0 && t == 0) s_p[j1] = i;  // assign row i to free column j1
            __syncthreads();                                   // B4

            if (pj1 == 0) break;
            j0 = j1;
            i0 = pj1;
            u_i0 = s_u[i0];                       // post-B4: updates visible
        }
    }

    // col4row[row-1] = col-1 for matched columns
#pragma unroll
    for (int k = 0; k < CPT; k++) {
        int j = jbase + k;
        int pj = s_p[j];
        if (pj > 0) s_col4row[pj - 1] = j - 1;
    }
    __syncthreads();

    // argsort by prediction index (all distinct)
    if (t < MM) {
        int pred = s_col4row[t];
        int rank = 0;
#pragma unroll
        for (int g = 0; g < MM; g++) rank += (s_col4row[g] < pred) ? 1 : 0;
        out_row[b * MM + rank] = (float)pred;
        out_col[b * MM + rank] = (float)t;
    }
}

extern "C" void kernel_launch(void* const* d_in, const int* in_sizes, int n_in,
                              void* d_out, int out_size)
{
    const float* ps = (const float*)d_in[0];   // [64,2048,2]
    const float* pb = (const float*)d_in[1];   // [64,2048,4]
    const int*   gs = (const int*)  d_in[2];   // [64,64]
    const float* gb = (const float*)d_in[3];   // [64,64,4]
    float* out = (float*)d_out;

    dim3 g1(NN / 64, BB);
    cost_kernel<<<g1, 512>>>(ps, pb, gs, gb, out);

    const long cost_elems = (long)BB * NN * MM;
    const long idx_elems  = (long)BB * MM;
    if (out_size >= cost_elems + 2 * idx_elems) {
        float* row_out = out + cost_elems;
        float* col_out = row_out + idx_elems;
        hungarian_kernel<<<BB, TPB>>>(row_out, col_out);
    }
}

// round 3
// speedup vs baseline: 1.5651x; 1.0285x over previous
#include <cuda_runtime.h>
#include <cuda_bf16.h>
#include <math_constants.h>

#define BB 64
#define NN 2048
#define MM 64
#define TPB 128      // hungarian threads per block (4 warps)
#define CPT 16       // columns per thread (TPB*CPT == NN)

// Transposed cost scratch: costT[b][m][n] (float; exact f32 values).
__device__ float g_costT[BB * MM * NN];

// ---------------------------------------------------------------------------
// Kernel 1: cost[b][n][m] = -ps[b][n][gs[b][m]] + sum_d |pb[b][n][d]-gb[b][m][d]|
// ---------------------------------------------------------------------------
__global__ void __launch_bounds__(512) cost_kernel(
    const float* __restrict__ ps, const float* __restrict__ pb,
    const int* __restrict__ gs, const float* __restrict__ gb,
    float* __restrict__ cost_out)
{
    const int b  = blockIdx.y;
    const int n0 = blockIdx.x * 64;
    const int t  = threadIdx.x;

    __shared__ float s_ps[64 * 2];
    __shared__ float s_pb[64 * 4];
    __shared__ float s_gb[64 * 4];
    __shared__ int   s_gs[64];
    __shared__ float tile[64][65];

    if (t < 128) s_ps[t] = ps[(b * NN + n0) * 2 + t];
    if (t < 256) s_pb[t] = pb[(b * NN + n0) * 4 + t];
    else         s_gb[t - 256] = gb[b * MM * 4 + (t - 256)];
    if (t < 64)  s_gs[t] = gs[b * MM + t];
    __syncthreads();

    const int out_base = (b * NN + n0) * MM;
#pragma unroll
    for (int k = 0; k < 8; k++) {
        int idx = t + k * 512;
        int nl = idx >> 6;
        int m  = idx & 63;
        float pres = -s_ps[nl * 2 + s_gs[m]];
        float l1 = fabsf(s_pb[nl * 4 + 0] - s_gb[m * 4 + 0]);
        l1 = l1 + fabsf(s_pb[nl * 4 + 1] - s_gb[m * 4 + 1]);
        l1 = l1 + fabsf(s_pb[nl * 4 + 2] - s_gb[m * 4 + 2]);
        l1 = l1 + fabsf(s_pb[nl * 4 + 3] - s_gb[m * 4 + 3]);
        float cv = pres + l1;
        tile[nl][m] = cv;
        cost_out[out_base + idx] = cv;
    }
    __syncthreads();

    const int ct_base = b * (MM * NN) + n0;
#pragma unroll
    for (int k = 0; k < 8; k++) {
        int idx = t + k * 512;
        int m  = idx >> 6;
        int nl = idx & 63;
        g_costT[ct_base + m * NN + nl] = tile[nl][m];
    }
}

// monotone map float -> uint (order preserving)
__device__ __forceinline__ unsigned fmap(float x) {
    unsigned u = __float_as_uint(x);
    return (u & 0x80000000u) ? ~u : (u | 0x80000000u);
}
__device__ __forceinline__ float funmap(unsigned m) {
    unsigned u = (m & 0x80000000u) ? (m ^ 0x80000000u) : ~m;
    return __uint_as_float(u);
}

// ---------------------------------------------------------------------------
// Kernel 2: exact replication of the reference's degenerate Hungarian loop.
// 2 barriers / chain iteration; u folded out of the fp32 scan; speculative
// next-row prefetch overlapped with the exact-f64 selection.
// Columns 0-based (0..2047); rows 1..64; p[j]=0 means unmatched.
// ---------------------------------------------------------------------------
__global__ void __launch_bounds__(TPB) hungarian_kernel(
    float* __restrict__ out_row, float* __restrict__ out_col)
{
    const int b    = blockIdx.x;
    const int t    = threadIdx.x;
    const float* crow_base = g_costT + (size_t)b * MM * NN;

    __shared__ double s_u[MM + 1];
    __shared__ int    s_p[NN];
    __shared__ int    s_ncand;
    __shared__ double s_cval[256];
    __shared__ int    s_cidx[256];
    __shared__ unsigned long long s_speckey[2];
    __shared__ double s_delta;
    __shared__ int    s_j1, s_pj1;
    __shared__ int    s_col4row[MM];

    const float NEG_INF = -CUDART_INF_F;

    double v_loc[CPT];
    float  vf_loc[CPT];
    int    rowOf[CPT];
#pragma unroll
    for (int k = 0; k < CPT; k++) { v_loc[k] = 0.0; vf_loc[k] = 0.0f; rowOf[k] = 0; }

    for (int j = t; j < NN; j += TPB) s_p[j] = 0;
    if (t <= MM) s_u[t] = 0.0;
    if (t == 0) { s_ncand = 0; s_speckey[0] = ~0ULL; s_speckey[1] = ~0ULL; }
    __syncthreads();

    const int jbase = t * CPT;     // first 0-based column owned by this thread
    float Dsum = 0.0f;             // running sum of |delta| for fp32 error band
    int   itp  = 0;                // iteration parity for speckey double-buffer

    float cc[CPT];
    int loadedRow = 1;
    {   // prefetch row 1
        const float4* r4 = reinterpret_cast<const float4*>(crow_base + jbase);
        float4 a = __ldg(r4+0), c = __ldg(r4+1), d = __ldg(r4+2), e = __ldg(r4+3);
        cc[0]=a.x;cc[1]=a.y;cc[2]=a.z;cc[3]=a.w; cc[4]=c.x;cc[5]=c.y;cc[6]=c.z;cc[7]=c.w;
        cc[8]=d.x;cc[9]=d.y;cc[10]=d.z;cc[11]=d.w; cc[12]=e.x;cc[13]=e.y;cc[14]=e.z;cc[15]=e.w;
    }

    for (int i = 1; i <= MM; i++) {
        if (loadedRow != i) {
            const float4* r4 = reinterpret_cast<const float4*>(crow_base + (size_t)(i-1)*NN + jbase);
            float4 a = __ldg(r4+0), c = __ldg(r4+1), d = __ldg(r4+2), e = __ldg(r4+3);
            cc[0]=a.x;cc[1]=a.y;cc[2]=a.z;cc[3]=a.w; cc[4]=c.x;cc[5]=c.y;cc[6]=c.z;cc[7]=c.w;
            cc[8]=d.x;cc[9]=d.y;cc[10]=d.z;cc[11]=d.w; cc[12]=e.x;cc[13]=e.y;cc[14]=e.z;cc[15]=e.w;
            loadedRow = i;
        }
        double u_i0 = s_u[i];      // fresh row: 0.0

        for (;;) {
            // ---------------- fp32 scan: x = c - vf (u folded out) ----------
            float x[CPT];
#pragma unroll
            for (int k = 0; k < CPT; k++) x[k] = cc[k] - vf_loc[k];
            float m01 = fminf(x[0], x[1]),  m23 = fminf(x[2], x[3]);
            float m45 = fminf(x[4], x[5]),  m67 = fminf(x[6], x[7]);
            float m89 = fminf(x[8], x[9]),  mab = fminf(x[10], x[11]);
            float mcd = fminf(x[12], x[13]), mef = fminf(x[14], x[15]);
            float mA = fminf(fminf(m01, m23), fminf(m45, m67));
            float mB = fminf(fminf(m89, mab), fminf(mcd, mef));
            float m  = fminf(mA, mB);

            unsigned mym  = fmap(m);
            unsigned wmin = __reduce_min_sync(0xffffffffu, mym);
            float wm  = funmap(wmin);
            float thr = wm + (6e-6f + 8e-7f * Dsum + 2e-7f * fabsf(wm));

            // candidates: exact f64 verify (rare)
            if (m <= thr) {
#pragma unroll
                for (int k = 0; k < CPT; k++) {
                    if (x[k] <= thr) {
                        double cur64 = ((double)cc[k] - u_i0) - v_loc[k];
                        int slot = atomicAdd(&s_ncand, 1);
                        if (slot < 256) { s_cval[slot] = cur64; s_cidx[slot] = jbase + k; }
                    }
                }
            }
            // fp32 warp winner publishes speculation key
            if (mym == wmin) {
                int kw = 0;
#pragma unroll
                for (int k = CPT - 1; k >= 0; k--) if (x[k] == m) kw = k;
                int jj = jbase + kw;
                int pj = s_p[jj];
                unsigned long long key = ((unsigned long long)mym << 32) |
                                         (unsigned)((jj << 7) | pj);
                atomicMin(&s_speckey[itp & 1], key);
            }
            __syncthreads();                                       // B2

            // speculative next-row prefetch (all threads, same decision)
            {
                unsigned long long key = s_speckey[itp & 1];
                int specrow = (int)(key & 127ULL);
                if (specrow != 0 && specrow != loadedRow) {
                    const float4* r4 = reinterpret_cast<const float4*>(
                        crow_base + (size_t)(specrow-1)*NN + jbase);
                    float4 a = __ldg(r4+0), c = __ldg(r4+1), d = __ldg(r4+2), e = __ldg(r4+3);
                    cc[0]=a.x;cc[1]=a.y;cc[2]=a.z;cc[3]=a.w; cc[4]=c.x;cc[5]=c.y;cc[6]=c.z;cc[7]=c.w;
                    cc[8]=d.x;cc[9]=d.y;cc[10]=d.z;cc[11]=d.w; cc[12]=e.x;cc[13]=e.y;cc[14]=e.z;cc[15]=e.w;
                    loadedRow = specrow;
                }
            }
            if (t == 0) {
                int nc = s_ncand; if (nc > 256) nc = 256;
                double best = 1e308; int bidx = 1 << 30;
                for (int q = 0; q < nc; q++) {
                    double kv = s_cval[q]; int ix = s_cidx[q];
                    if (kv < best || (kv == best && ix < bidx)) { best = kv; bidx = ix; }
                }
                s_delta = best;
                s_j1    = bidx;
                s_pj1   = s_p[bidx];
                s_ncand = 0;
                s_speckey[(itp + 1) & 1] = ~0ULL;   // reset slot for next iter
            }
            __syncthreads();                                       // B3

            const double delta = s_delta;
            const int    j1    = s_j1;
            const int    pj1   = s_pj1;
            itp++;
            Dsum += fabsf((float)delta);

            // dual updates for used columns (vf == -INF marks used)
#pragma unroll
            for (int k = 0; k < CPT; k++) {
                if (vf_loc[k] == NEG_INF) {
                    v_loc[k] -= delta;
                    s_u[rowOf[k]] += delta;     // distinct rows: no conflicts
                }
            }
            if (t == 0) s_u[i] += delta;        // virtual column 0 (p[0] = i)

            if (pj1 == 0) {
                if (t == 0) s_p[j1] = i;        // assign row i to free column j1
                // restore fp32 v copies for this augment's used columns
#pragma unroll
                for (int k = 0; k < CPT; k++)
                    if (vf_loc[k] == NEG_INF) vf_loc[k] = (float)v_loc[k];
                // deterministic prefetch of next augment's first row
                if (i < MM && loadedRow != i + 1) {
                    const float4* r4 = reinterpret_cast<const float4*>(
                        crow_base + (size_t)i*NN + jbase);
                    float4 a = __ldg(r4+0), c = __ldg(r4+1), d = __ldg(r4+2), e = __ldg(r4+3);
                    cc[0]=a.x;cc[1]=a.y;cc[2]=a.z;cc[3]=a.w; cc[4]=c.x;cc[5]=c.y;cc[6]=c.z;cc[7]=c.w;
                    cc[8]=d.x;cc[9]=d.y;cc[10]=d.z;cc[11]=d.w; cc[12]=e.x;cc[13]=e.y;cc[14]=e.z;cc[15]=e.w;
                    loadedRow = i + 1;
                }
                __syncthreads();   // order s_p write vs next augment's reads
                break;
            }

            // mark j1 used (owner); next scan row = pj1
            if (j1 >= jbase && j1 < jbase + CPT) {
                int km = j1 - jbase;
#pragma unroll
                for (int kk = 0; kk < CPT; kk++)
                    if (kk == km) { vf_loc[kk] = NEG_INF; rowOf[kk] = pj1; }
            }
            u_i0 = s_u[pj1];   // untouched this iteration (j1 was unused)
            if (loadedRow != pj1) {   // speculation missed
                const float4* r4 = reinterpret_cast<const float4*>(
                    crow_base + (size_t)(pj1-1)*NN + jbase);
                float4 a = __ldg(r4+0), c = __ldg(r4+1), d = __ldg(r4+2), e = __ldg(r4+3);
                cc[0]=a.x;cc[1]=a.y;cc[2]=a.z;cc[3]=a.w; cc[4]=c.x;cc[5]=c.y;cc[6]=c.z;cc[7]=c.w;
                cc[8]=d.x;cc[9]=d.y;cc[10]=d.z;cc[11]=d.w; cc[12]=e.x;cc[13]=e.y;cc[14]=e.z;cc[15]=e.w;
                loadedRow = pj1;
            }
        }
    }

    // col4row[row-1] = col (0-based) for matched columns
#pragma unroll
    for (int k = 0; k < CPT; k++) {
        int j = jbase + k;
        int pj = s_p[j];
        if (pj > 0) s_col4row[pj - 1] = j;
    }
    __syncthreads();

    // argsort by prediction index (all distinct)
    if (t < MM) {
        int pred = s_col4row[t];
        int rank = 0;
#pragma unroll
        for (int g = 0; g < MM; g++) rank += (s_col4row[g] < pred) ? 1 : 0;
        out_row[b * MM + rank] = (float)pred;
        out_col[b * MM + rank] = (float)t;
    }
}

extern "C" void kernel_launch(void* const* d_in, const int* in_sizes, int n_in,
                              void* d_out, int out_size)
{
    const float* ps = (const float*)d_in[0];   // [64,2048,2]
    const float* pb = (const float*)d_in[1];   // [64,2048,4]
    const int*   gs = (const int*)  d_in[2];   // [64,64]
    const float* gb = (const float*)d_in[3];   // [64,64,4]
    float* out = (float*)d_out;

    dim3 g1(NN / 64, BB);
    cost_kernel<<<g1, 512>>>(ps, pb, gs, gb, out);

    const long cost_elems = (long)BB * NN * MM;
    const long idx_elems  = (long)BB * MM;
    if (out_size >= cost_elems + 2 * idx_elems) {
        float* row_out = out + cost_elems;
        float* col_out = row_out + idx_elems;
        hungarian_kernel<<<BB, TPB>>>(row_out, col_out);
    }
}

// round 4
// speedup vs baseline: 3.4159x; 2.1825x over previous
#include <cuda_runtime.h>
#include <cuda_bf16.h>
#include <math_constants.h>

#define BB 64
#define NN 2048
#define MM 64

// Scratch: costT[b][m][n] (f32). Rewritten by cost_kernel every launch, then
// progressively poisoned (+INF on dirty columns) by hungarian_kernel.
__device__ float g_costT[BB * MM * NN];

// ---------------------------------------------------------------------------
// Kernel 1: cost[b][n][m] = -ps[b][n][gs[b][m]] + sum_d |pb[b][n][d]-gb[b][m][d]|
// ---------------------------------------------------------------------------
__global__ void __launch_bounds__(512) cost_kernel(
    const float* __restrict__ ps, const float* __restrict__ pb,
    const int* __restrict__ gs, const float* __restrict__ gb,
    float* __restrict__ cost_out)
{
    const int b  = blockIdx.y;
    const int n0 = blockIdx.x * 64;
    const int t  = threadIdx.x;

    __shared__ float s_ps[64 * 2];
    __shared__ float s_pb[64 * 4];
    __shared__ float s_gb[64 * 4];
    __shared__ int   s_gs[64];
    __shared__ float tile[64][65];

    if (t < 128) s_ps[t] = ps[(b * NN + n0) * 2 + t];
    if (t < 256) s_pb[t] = pb[(b * NN + n0) * 4 + t];
    else         s_gb[t - 256] = gb[b * MM * 4 + (t - 256)];
    if (t < 64)  s_gs[t] = gs[b * MM + t];
    __syncthreads();

    const int out_base = (b * NN + n0) * MM;
#pragma unroll
    for (int k = 0; k < 8; k++) {
        int idx = t + k * 512;
        int nl = idx >> 6;
        int m  = idx & 63;
        float pres = -s_ps[nl * 2 + s_gs[m]];
        float l1 = fabsf(s_pb[nl * 4 + 0] - s_gb[m * 4 + 0]);
        l1 = l1 + fabsf(s_pb[nl * 4 + 1] - s_gb[m * 4 + 1]);
        l1 = l1 + fabsf(s_pb[nl * 4 + 2] - s_gb[m * 4 + 2]);
        l1 = l1 + fabsf(s_pb[nl * 4 + 3] - s_gb[m * 4 + 3]);
        float cv = pres + l1;
        tile[nl][m] = cv;
        cost_out[out_base + idx] = cv;
    }
    __syncthreads();

    const int ct_base = b * (MM * NN) + n0;
#pragma unroll
    for (int k = 0; k < 8; k++) {
        int idx = t + k * 512;
        int m  = idx >> 6;
        int nl = idx & 63;
        g_costT[ct_base + m * NN + nl] = tile[nl][m];
    }
}

// monotone order-preserving maps
__device__ __forceinline__ unsigned fmapf(float x) {
    unsigned u = __float_as_uint(x);
    return (u & 0x80000000u) ? ~u : (u | 0x80000000u);
}
__device__ __forceinline__ float funmapf(unsigned m) {
    unsigned u = (m & 0x80000000u) ? (m ^ 0x80000000u) : ~m;
    return __uint_as_float(u);
}
__device__ __forceinline__ unsigned long long dmap(double d) {
    unsigned long long u = (unsigned long long)__double_as_longlong(d);
    return (u >> 63) ? ~u : (u | 0x8000000000000000ULL);
}
__device__ __forceinline__ double dunmap(unsigned long long m) {
    unsigned long long u = (m & 0x8000000000000000ULL) ? (m ^ 0x8000000000000000ULL) : ~m;
    return __longlong_as_double((long long)u);
}

__device__ __forceinline__ void prefetch_row(const float* rowp, int l) {
#pragma unroll
    for (int c = 0; c < 16; c++)
        asm volatile("prefetch.global.L1 [%0];" :: "l"(rowp + c * 128 + l * 4));
}

// ---------------------------------------------------------------------------
// Kernel 2: warp-synchronous exact replication of the reference loop.
// One warp per batch. Lane l owns columns {c*128 + l*4 + j : c=0..15, j=0..3}.
// Dirty (ever-used) columns are poisoned (+INF) in g_costT and handled exactly
// in f64 from a compact list; clean columns scanned by raw f32 cost.
// ---------------------------------------------------------------------------
__global__ void __launch_bounds__(32) hungarian_kernel(
    float* __restrict__ out_row, float* __restrict__ out_col)
{
    const int b = blockIdx.x;
    const int l = threadIdx.x;
    float* base = g_costT + (size_t)b * MM * NN;
    const unsigned FULL = 0xffffffffu;

    __shared__ double s_u[MM + 1];
    __shared__ int    s_p[NN];
    __shared__ float  s_dc[MM][64];     // saved original c for dirty cols: [row][entry]
    __shared__ signed char s_centry[NN];
    __shared__ int    s_col4row[MM];

    // per-lane dirty entry slots: entry e handled by lane e%32, slot e/32
    int    dcol0 = -1, dcol1 = -1;
    double dv0 = 0.0, dv1 = 0.0;
    int    drow0 = 0, drow1 = 0;
    int    used0 = 0, used1 = 0;
    int    nd = 0;                      // dirty count (lane-replicated)

    for (int j = l; j < NN; j += 32) { s_p[j] = 0; s_centry[j] = -1; }
#pragma unroll
    for (int k = 0; k < 3; k++) { int r = l + k * 32; if (r <= MM) s_u[r] = 0.0; }
    __syncwarp();

    for (int i = 1; i <= MM; i++) {
        int i0 = i;
        double u_i0 = s_u[i];

        for (;;) {
            const float* rowp = base + (size_t)(i0 - 1) * NN;
            const float4* r4 = reinterpret_cast<const float4*>(rowp);

            // ---- clean scan: stream row, build 32 pairs ----
            float pr[32];
            unsigned pf = 0;
#pragma unroll
            for (int c = 0; c < 16; c++) {
                float4 v = __ldg(r4 + c * 32 + l);
                pr[2*c]   = fminf(v.x, v.y);
                pr[2*c+1] = fminf(v.z, v.w);
                if (v.y < v.x) pf |= (1u << (2*c));
                if (v.w < v.z) pf |= (1u << (2*c+1));
            }
            float tr[32];
#pragma unroll
            for (int q = 0; q < 32; q++) tr[q] = pr[q];
#pragma unroll
            for (int s = 16; s > 0; s >>= 1) {
#pragma unroll
                for (int q = 0; q < 16; q++)
                    if (q < s) tr[q] = fminf(tr[q], tr[q + s]);
            }
            float m = tr[0];

            unsigned wmu = __reduce_min_sync(FULL, fmapf(m));
            float wm = funmapf(wmu);

            // lane-local lowest matching column (k ascending == col ascending)
            unsigned mycol = 0xffffffffu;
            if (fmapf(m) == wmu) {
                int bestq = 0;
#pragma unroll
                for (int q = 31; q >= 0; q--) if (pr[q] == wm) bestq = q;
                int k = 2 * bestq + (int)((pf >> bestq) & 1u);
                mycol = (unsigned)((k >> 2) * 128 + l * 4 + (k & 3));
            }
            unsigned jclean = __reduce_min_sync(FULL, mycol);

            // ---- dirty scan: exact f64, ((c - u) - v), index tie-break ----
            unsigned long long bk = ~0ULL;
            unsigned bcol = 0xffffffffu;
            if (l < nd && !used0) {
                double cur = ((double)s_dc[i0 - 1][l] - u_i0) - dv0;
                unsigned long long k2 = dmap(cur);
                if (k2 < bk || (k2 == bk && (unsigned)dcol0 < bcol)) { bk = k2; bcol = (unsigned)dcol0; }
            }
            if (l + 32 < nd && !used1) {
                double cur = ((double)s_dc[i0 - 1][l + 32] - u_i0) - dv1;
                unsigned long long k2 = dmap(cur);
                if (k2 < bk || (k2 == bk && (unsigned)dcol1 < bcol)) { bk = k2; bcol = (unsigned)dcol1; }
            }
            unsigned hi   = (unsigned)(bk >> 32);
            unsigned hmin = __reduce_min_sync(FULL, hi);
            unsigned lo   = (hi == hmin) ? (unsigned)bk : 0xffffffffu;
            unsigned lmin = __reduce_min_sync(FULL, lo);
            unsigned cnd  = (hi == hmin && (unsigned)bk == lmin) ? bcol : 0xffffffffu;
            unsigned dcolw = __reduce_min_sync(FULL, cnd);
            bool haveDirty = (hmin != 0xffffffffu) || (lmin != 0xffffffffu);
            unsigned long long dkey = ((unsigned long long)hmin << 32) | lmin;

            // ---- prefetch both candidate next rows ----
            int pclean = s_p[jclean];
            int pdirty = haveDirty ? s_p[dcolw] : 0;
            if (pclean != 0) prefetch_row(base + (size_t)(pclean - 1) * NN, l);
            if (pdirty != 0 && pdirty != pclean) prefetch_row(base + (size_t)(pdirty - 1) * NN, l);

            // ---- exact selection ----
            double cleancur = (double)wm - u_i0;         // v = 0 exactly
            unsigned long long ckey = dmap(cleancur);
            bool pickDirty = haveDirty &&
                (dkey < ckey || (dkey == ckey && dcolw < jclean));
            double delta = pickDirty ? dunmap(dkey) : cleancur;
            int    j1    = pickDirty ? (int)dcolw : (int)jclean;
            int    pj1   = pickDirty ? pdirty : pclean;

            // ---- dual updates (reference order) ----
            if (l < nd && used0)      { dv0 -= delta; s_u[drow0] += delta; }
            if (l + 32 < nd && used1) { dv1 -= delta; s_u[drow1] += delta; }
            if (l == 0) s_u[i] += delta;     // virtual column 0 (p[0] = i)
            __syncwarp();

            if (pj1 == 0) {
                if (l == 0) s_p[j1] = i;
                used0 = 0; used1 = 0;
                if (i < MM) prefetch_row(base + (size_t)i * NN, l);  // row i+1
                __syncwarp();
                break;
            }

            // mark j1 used; create entry if it was a clean matched column
            int e1 = (int)s_centry[j1];
            if (e1 < 0) {
                e1 = nd;
                if ((e1 & 31) == l) {
                    if (e1 < 32) { dcol0 = j1; dv0 = 0.0; }
                    else         { dcol1 = j1; dv1 = 0.0; }
                }
                if (l == 0) s_centry[j1] = (signed char)e1;
                // save original c for all 64 rows, poison costT column
                float v0 = __ldg(base + (size_t)l * NN + j1);
                float v1 = __ldg(base + (size_t)(l + 32) * NN + j1);
                s_dc[l][e1]      = v0;
                s_dc[l + 32][e1] = v1;
                base[(size_t)l * NN + j1]        = CUDART_INF_F;
                base[(size_t)(l + 32) * NN + j1] = CUDART_INF_F;
                __threadfence_block();
                nd++;
            }
            if ((e1 & 31) == l) {
                if (e1 < 32) { used0 = 1; drow0 = pj1; }
                else         { used1 = 1; drow1 = pj1; }
            }
            __syncwarp();

            i0 = pj1;
            u_i0 = s_u[i0];
        }
    }

    // col4row[row-1] = matched column (0-based)
    for (int j = l; j < NN; j += 32) {
        int pj = s_p[j];
        if (pj > 0) s_col4row[pj - 1] = j;
    }
    __syncwarp();

    // argsort by prediction index (all distinct)
    for (int r = l; r < MM; r += 32) {
        int pred = s_col4row[r];
        int rank = 0;
#pragma unroll
        for (int g = 0; g < MM; g++) rank += (s_col4row[g] < pred) ? 1 : 0;
        out_row[b * MM + rank] = (float)pred;
        out_col[b * MM + rank] = (float)r;
    }
}

extern "C" void kernel_launch(void* const* d_in, const int* in_sizes, int n_in,
                              void* d_out, int out_size)
{
    const float* ps = (const float*)d_in[0];   // [64,2048,2]
    const float* pb = (const float*)d_in[1];   // [64,2048,4]
    const int*   gs = (const int*)  d_in[2];   // [64,64]
    const float* gb = (const float*)d_in[3];   // [64,64,4]
    float* out = (float*)d_out;

    dim3 g1(NN / 64, BB);
    cost_kernel<<<g1, 512>>>(ps, pb, gs, gb, out);

    const long cost_elems = (long)BB * NN * MM;
    const long idx_elems  = (long)BB * MM;
    if (out_size >= cost_elems + 2 * idx_elems) {
        float* row_out = out + cost_elems;
        float* col_out = row_out + idx_elems;
        hungarian_kernel<<<BB, 32>>>(row_out, col_out);
    }
}

// round 5
// speedup vs baseline: 4.4908x; 1.3147x over previous
#include <cuda_runtime.h>
#include <cuda_bf16.h>
#include <math_constants.h>

#define BB 64
#define NN 2048
#define MM 64
#define NSEG 64          // NN/32 segments of 32 columns

// Scratch: costT[b][m][n] (f32), rewritten every launch, then poisoned (+INF
// on dirty columns). Segment min/argmin tables built by cost_kernel.
__device__ float g_costT[BB * MM * NN];
__device__ float g_segmin[BB * MM * NSEG];
__device__ short g_segarg[BB * MM * NSEG];

// ---------------------------------------------------------------------------
// Kernel 1: cost[b][n][m] = -ps[b][n][gs[b][m]] + sum_d |pb[b][n][d]-gb[b][m][d]|
// Also emits per-(row m, 32-col segment) min + first-argmin of costT.
// ---------------------------------------------------------------------------
__global__ void __launch_bounds__(512) cost_kernel(
    const float* __restrict__ ps, const float* __restrict__ pb,
    const int* __restrict__ gs, const float* __restrict__ gb,
    float* __restrict__ cost_out)
{
    const int b  = blockIdx.y;
    const int n0 = blockIdx.x * 64;
    const int t  = threadIdx.x;

    __shared__ float s_ps[64 * 2];
    __shared__ float s_pb[64 * 4];
    __shared__ float s_gb[64 * 4];
    __shared__ int   s_gs[64];
    __shared__ float tile[64][65];

    if (t < 128) s_ps[t] = ps[(b * NN + n0) * 2 + t];
    if (t < 256) s_pb[t] = pb[(b * NN + n0) * 4 + t];
    else         s_gb[t - 256] = gb[b * MM * 4 + (t - 256)];
    if (t < 64)  s_gs[t] = gs[b * MM + t];
    __syncthreads();

    const int out_base = (b * NN + n0) * MM;
#pragma unroll
    for (int k = 0; k < 8; k++) {
        int idx = t + k * 512;
        int nl = idx >> 6;
        int m  = idx & 63;
        float pres = -s_ps[nl * 2 + s_gs[m]];
        float l1 = fabsf(s_pb[nl * 4 + 0] - s_gb[m * 4 + 0]);
        l1 = l1 + fabsf(s_pb[nl * 4 + 1] - s_gb[m * 4 + 1]);
        l1 = l1 + fabsf(s_pb[nl * 4 + 2] - s_gb[m * 4 + 2]);
        l1 = l1 + fabsf(s_pb[nl * 4 + 3] - s_gb[m * 4 + 3]);
        float cv = pres + l1;
        tile[nl][m] = cv;
        cost_out[out_base + idx] = cv;
    }
    __syncthreads();

    const int ct_base = b * (MM * NN) + n0;
#pragma unroll
    for (int k = 0; k < 8; k++) {
        int idx = t + k * 512;
        int m  = idx >> 6;
        int nl = idx & 63;
        g_costT[ct_base + m * NN + nl] = tile[nl][m];
    }

    // segment min + first-argmin: this block covers segments n0/32 and n0/32+1
    if (t < 128) {
        int m = t & 63;
        int h = t >> 6;              // 0 or 1: which 32-col half
        float best = CUDART_INF_F; int barg = 0;
#pragma unroll
        for (int nl = 0; nl < 32; nl++) {
            float v = tile[h * 32 + nl][m];
            if (v < best) { best = v; barg = h * 32 + nl; }
        }
        int seg = (n0 >> 5) + h;
        g_segmin[(b * MM + m) * NSEG + seg] = best;
        g_segarg[(b * MM + m) * NSEG + seg] = (short)(n0 + barg);
    }
}

// monotone order-preserving maps
__device__ __forceinline__ unsigned fmapf(float x) {
    unsigned u = __float_as_uint(x);
    return (u & 0x80000000u) ? ~u : (u | 0x80000000u);
}
__device__ __forceinline__ float funmapf(unsigned m) {
    unsigned u = (m & 0x80000000u) ? (m ^ 0x80000000u) : ~m;
    return __uint_as_float(u);
}
__device__ __forceinline__ unsigned long long dmap(double d) {
    unsigned long long u = (unsigned long long)__double_as_longlong(d);
    return (u >> 63) ? ~u : (u | 0x8000000000000000ULL);
}
__device__ __forceinline__ double dunmap(unsigned long long m) {
    unsigned long long u = (m & 0x8000000000000000ULL) ? (m ^ 0x8000000000000000ULL) : ~m;
    return __longlong_as_double((long long)u);
}

// ---------------------------------------------------------------------------
// Kernel 2: warp-synchronous exact replication of the reference loop.
// Clean columns (v==0): served by the incremental segment-min table (smem only).
// Dirty columns (ever-used, <=63): exact f64 from a compact register list.
// ---------------------------------------------------------------------------
__global__ void __launch_bounds__(32) hungarian_kernel(
    float* __restrict__ out_row, float* __restrict__ out_col)
{
    const int b = blockIdx.x;
    const int l = threadIdx.x;
    float* base = g_costT + (size_t)b * MM * NN;
    const unsigned FULL = 0xffffffffu;

    __shared__ double s_u[MM + 1];
    __shared__ int    s_p[NN];
    __shared__ float  s_dc[MM][64];       // saved original c for dirty cols
    __shared__ signed char s_centry[NN];
    __shared__ float  s_segmin[MM][NSEG];
    __shared__ short  s_segarg[MM][NSEG];
    __shared__ int    s_col4row[MM];

    // per-lane dirty entry slots: entry e -> lane e%32, slot e/32
    int    dcol0 = -1, dcol1 = -1;
    double dv0 = 0.0, dv1 = 0.0;
    int    drow0 = 0, drow1 = 0;
    int    used0 = 0, used1 = 0;
    int    nd = 0;

    for (int j = l; j < NN; j += 32) { s_p[j] = 0; s_centry[j] = -1; }
#pragma unroll
    for (int k = 0; k < 3; k++) { int r = l + k * 32; if (r <= MM) s_u[r] = 0.0; }
    {   // load segment tables (coalesced)
        const float* gm = g_segmin + (size_t)b * MM * NSEG;
        const short* ga = g_segarg + (size_t)b * MM * NSEG;
        float* sm = &s_segmin[0][0];
        short* sa = &s_segarg[0][0];
#pragma unroll 8
        for (int idx = l; idx < MM * NSEG; idx += 32) { sm[idx] = gm[idx]; sa[idx] = ga[idx]; }
    }
    __syncwarp();

    for (int i = 1; i <= MM; i++) {
        int i0 = i;
        double u_i0 = s_u[i];

        for (;;) {
            // ---- clean scan: 2 LDS + 2 REDUX via segment table ----
            float a  = s_segmin[i0 - 1][l];
            float b2 = s_segmin[i0 - 1][l + 32];
            float mv = fminf(a, b2);
            unsigned wmin = __reduce_min_sync(FULL, fmapf(mv));
            float wm = funmapf(wmin);
            unsigned segc = (fmapf(a) == wmin) ? (unsigned)l :
                            ((fmapf(b2) == wmin) ? (unsigned)(l + 32) : 0xffffffffu);
            unsigned sseg = __reduce_min_sync(FULL, segc);
            int jclean = (int)s_segarg[i0 - 1][sseg];

            // ---- dirty scan: exact f64, ((c - u) - v), index tie-break ----
            unsigned long long bk = ~0ULL;
            unsigned bcol = 0xffffffffu;
            if (l < nd && !used0) {
                double cur = ((double)s_dc[i0 - 1][l] - u_i0) - dv0;
                unsigned long long k2 = dmap(cur);
                if (k2 < bk || (k2 == bk && (unsigned)dcol0 < bcol)) { bk = k2; bcol = (unsigned)dcol0; }
            }
            if (l + 32 < nd && !used1) {
                double cur = ((double)s_dc[i0 - 1][l + 32] - u_i0) - dv1;
                unsigned long long k2 = dmap(cur);
                if (k2 < bk || (k2 == bk && (unsigned)dcol1 < bcol)) { bk = k2; bcol = (unsigned)dcol1; }
            }
            unsigned hi   = (unsigned)(bk >> 32);
            unsigned hmin = __reduce_min_sync(FULL, hi);
            unsigned lo   = (hi == hmin) ? (unsigned)bk : 0xffffffffu;
            unsigned lmin = __reduce_min_sync(FULL, lo);
            unsigned cnd  = (hi == hmin && (unsigned)bk == lmin) ? bcol : 0xffffffffu;
            unsigned dcolw = __reduce_min_sync(FULL, cnd);
            bool haveDirty = (dcolw != 0xffffffffu);
            unsigned long long dkey = ((unsigned long long)hmin << 32) | lmin;

            int pclean = s_p[jclean];
            int pdirty = haveDirty ? s_p[dcolw] : 0;

            // ---- exact selection ----
            double cleancur = (double)wm - u_i0;      // v = 0 exactly on clean
            unsigned long long ckey = dmap(cleancur);
            bool pickDirty = haveDirty &&
                (dkey < ckey || (dkey == ckey && dcolw < (unsigned)jclean));
            double delta = pickDirty ? dunmap(dkey) : cleancur;
            int    j1    = pickDirty ? (int)dcolw : jclean;
            int    pj1   = pickDirty ? pdirty : pclean;

            // ---- dual updates (reference order) ----
            if (l < nd && used0)      { dv0 -= delta; s_u[drow0] += delta; }
            if (l + 32 < nd && used1) { dv1 -= delta; s_u[drow1] += delta; }
            if (l == 0) s_u[i] += delta;              // virtual column 0 (p[0]=i)
            __syncwarp();

            if (pj1 == 0) {
                if (l == 0) s_p[j1] = i;
                used0 = 0; used1 = 0;
                __syncwarp();
                break;
            }

            // ---- mark j1 used; first time: poison column + update seg table ----
            int e1 = (int)s_centry[j1];
            if (e1 < 0) {
                e1 = nd;
                if ((e1 & 31) == l) {
                    if (e1 < 32) { dcol0 = j1; dv0 = 0.0; }
                    else         { dcol1 = j1; dv1 = 0.0; }
                }
                if (l == 0) s_centry[j1] = (signed char)e1;
                // save original values, poison (lane l owns rows l, l+32)
                float v0 = base[(size_t)l * NN + j1];
                float v1 = base[(size_t)(l + 32) * NN + j1];
                s_dc[l][e1]      = v0;
                s_dc[l + 32][e1] = v1;
                base[(size_t)l * NN + j1]        = CUDART_INF_F;
                base[(size_t)(l + 32) * NN + j1] = CUDART_INF_F;
                nd++;
                // recompute this segment's min/argmin for rows l and l+32
                int sg = j1 >> 5;
#pragma unroll
                for (int rh = 0; rh < 2; rh++) {
                    int rr = l + rh * 32;
                    const float4* sp = reinterpret_cast<const float4*>(
                        base + (size_t)rr * NN + (sg << 5));
                    float bst = CUDART_INF_F; int ba = 0;
#pragma unroll
                    for (int c2 = 0; c2 < 8; c2++) {
                        float4 v = sp[c2];
                        if (v.x < bst) { bst = v.x; ba = c2 * 4 + 0; }
                        if (v.y < bst) { bst = v.y; ba = c2 * 4 + 1; }
                        if (v.z < bst) { bst = v.z; ba = c2 * 4 + 2; }
                        if (v.w < bst) { bst = v.w; ba = c2 * 4 + 3; }
                    }
                    s_segmin[rr][sg] = bst;
                    s_segarg[rr][sg] = (short)((sg << 5) + ba);
                }
            }
            if ((e1 & 31) == l) {
                if (e1 < 32) { used0 = 1; drow0 = pj1; }
                else         { used1 = 1; drow1 = pj1; }
            }
            __syncwarp();

            i0 = pj1;
            u_i0 = s_u[i0];
        }
    }

    // col4row[row-1] = matched column (0-based)
    for (int j = l; j < NN; j += 32) {
        int pj = s_p[j];
        if (pj > 0) s_col4row[pj - 1] = j;
    }
    __syncwarp();

    // argsort by prediction index (all distinct)
    for (int r = l; r < MM; r += 32) {
        int pred = s_col4row[r];
        int rank = 0;
#pragma unroll
        for (int g = 0; g < MM; g++) rank += (s_col4row[g] < pred) ? 1 : 0;
        out_row[b * MM + rank] = (float)pred;
        out_col[b * MM + rank] = (float)r;
    }
}

extern "C" void kernel_launch(void* const* d_in, const int* in_sizes, int n_in,
                              void* d_out, int out_size)
{
    const float* ps = (const float*)d_in[0];   // [64,2048,2]
    const float* pb = (const float*)d_in[1];   // [64,2048,4]
    const int*   gs = (const int*)  d_in[2];   // [64,64]
    const float* gb = (const float*)d_in[3];   // [64,64,4]
    float* out = (float*)d_out;

    dim3 g1(NN / 64, BB);
    cost_kernel<<<g1, 512>>>(ps, pb, gs, gb, out);

    const long cost_elems = (long)BB * NN * MM;
    const long idx_elems  = (long)BB * MM;
    if (out_size >= cost_elems + 2 * idx_elems) {
        float* row_out = out + cost_elems;
        float* col_out = row_out + idx_elems;
        hungarian_kernel<<<BB, 32>>>(row_out, col_out);
    }
}